// round 6
// baseline (speedup 1.0000x reference)
#include <cuda_runtime.h>

// ---- problem constants ----
#define Gg      180
#define NATOMS  64
#define NRAD    8
#define NANG    16
#define NACC    128
#define RMAXI   13
#define BDIM    27
#define NROWS   (BDIM*BDIM)        // 729 k-rows
#define CSPLIT  11
#define NTH     64
#define CAPW    1024               // per-warp compacted-list capacity (u16)
#define SHIFT_C 1.25f

#define A_F   (0.2f)
#define RO_F  (2.5f)

// scratch (static __device__: no allocation)
__device__ float g_part[NATOMS * CSPLIT * NACC];
__device__ int   g_cnt[NATOMS];          // self-resetting arrival counters

__global__ __launch_bounds__(NTH, 5)
void proj_kernel(const float* __restrict__ rho, const float* __restrict__ pos,
                 const float* __restrict__ W, float* __restrict__ out)
{
    const int split = blockIdx.x;
    const int atom  = blockIdx.y;
    const int tid   = threadIdx.x;
    const int warp  = tid >> 5;
    const int lane  = tid & 31;

    __shared__ float sOfs[3][BDIM];
    __shared__ int   sIdx[3][BDIM];
    __shared__ unsigned short slist[2 * CAPW];
    __shared__ int   scnt[2];
    __shared__ int   s_old;
    __shared__ float sred[2][NACC];

    // ---------- per-dimension stencil setup ----------
    for (int w = tid; w < 3 * BDIM; w += NTH) {
        int dim = w / BDIM;
        int o   = w - dim * BDIM;
        int off = o - RMAXI;
        float p  = pos[atom * 3 + dim];
        float cm = rintf(p / A_F);                 // round-half-even == jnp.round
        float dr = __fadd_rn(p, -__fmul_rn(A_F, cm));
        int ci = (int)cm + off;
        if (ci < 0)   ci += Gg;
        if (ci >= Gg) ci -= Gg;
        sIdx[dim][o] = ci;
        sOfs[dim][o] = __fadd_rn(__fmul_rn((float)off, A_F), -dr);
    }
    __syncthreads();

    // ---------- phase 1: per-warp compaction, rows round-robin across splits ----------
    const float ro2 = RO_F * RO_F;
    const int nrows = (NROWS - split + CSPLIT - 1) / CSPLIT;   // rows r = split + 11*ri
    const int ntot  = nrows * BDIM;
    const int nit   = (ntot + NTH - 1) / NTH;
    int wbase = 0;
    #pragma unroll 1
    for (int it = 0; it < nit; ++it) {
        int idx = it * NTH + tid;
        bool valid = idx < ntot;
        unsigned ii = valid ? (unsigned)idx : 0u;
        unsigned ri = ii / 27u;
        unsigned kk = ii - ri * 27u;
        unsigned r  = (unsigned)split + ri * CSPLIT;
        unsigned i  = r / 27u;
        unsigned j  = r - i * 27u;
        float x = sOfs[0][i], y = sOfs[1][j], z = sOfs[2][kk];
        float r2 = x * x + y * y + z * z;
        bool pred = valid && (r2 < ro2);
        unsigned mask = __ballot_sync(0xFFFFFFFFu, pred);
        if (pred) {
            int p = wbase + __popc(mask & ((1u << lane) - 1u));
            if (p < CAPW)
                slist[warp * CAPW + p] = (unsigned short)((i << 10) | (j << 5) | kk);
        }
        wbase += __popc(mask);
    }
    if (lane == 0) scnt[warp] = (wbase < CAPW) ? wbase : CAPW;
    __syncthreads();

    // ---------- phase 2: dense accumulation, shifted moment basis ----------
    float acc[NACC];                       // acc[k*16 + lm],  nu_k = sum base*s^k
    #pragma unroll
    for (int q = 0; q < NACC; ++q) acc[q] = 0.0f;

    {
        const int cnt = scnt[warp];
        const unsigned short* lst = &slist[warp * CAPW];
        int idx = lane;
        if (idx < cnt) {
            unsigned cell = lst[idx];
            int i0 = cell >> 10, j0 = (cell >> 5) & 31, k0 = cell & 31;
            float rv = __ldg(&rho[(sIdx[0][i0] * Gg + sIdx[1][j0]) * Gg + sIdx[2][k0]]);

            #pragma unroll 1
            while (true) {
                // prefetch next cell + density
                int nidx = idx + 32;
                bool more = nidx < cnt;
                unsigned ncell = 0; float nrv = 0.0f;
                if (more) {
                    ncell = lst[nidx];
                    int ni = ncell >> 10, nj = (ncell >> 5) & 31, nk = ncell & 31;
                    nrv = __ldg(&rho[(sIdx[0][ni] * Gg + sIdx[1][nj]) * Gg + sIdx[2][nk]]);
                }

                int i = cell >> 10, j = (cell >> 5) & 31, k = cell & 31;
                float x = sOfs[0][i], y = sOfs[1][j], z = sOfs[2][k];
                float r2 = x * x + y * y + z * z;
                float rinv = rsqrtf(fmaxf(r2, 1e-24f));
                float R  = r2 * rinv;
                float b  = RO_F - R;
                float s  = b - SHIFT_C;

                // t_k = r2*b^2*rho * s^k
                float t[NRAD];
                t[0] = r2 * (b * b) * rv;
                #pragma unroll
                for (int m = 1; m < NRAD; ++m) t[m] = t[m - 1] * s;

                float ux = x * rinv, uy = y * rinv, uz = z * rinv;
                float ux2 = ux * ux, uy2 = uy * uy, uz2 = uz * uz;

                // fused: per lm compute Y then 8 FMAs (keeps regs low)
                #define ACCY(lm, expr) { float yv = (expr);                         \
                    _Pragma("unroll")                                               \
                    for (int m = 0; m < NRAD; ++m)                                  \
                        acc[m * NANG + (lm)] = fmaf(t[m], yv, acc[m * NANG + (lm)]); }

                ACCY(0,  0.28209479177387814f)
                ACCY(1,  0.4886025119029199f * uy)
                ACCY(2,  0.4886025119029199f * uz)
                ACCY(3,  0.4886025119029199f * ux)
                ACCY(4,  0.5462742152960396f * (2.0f * ux * uy))
                ACCY(5,  1.0925484305920792f * (uy * uz))
                ACCY(6,  0.31539156525252005f * (3.0f * uz2 - 1.0f))
                ACCY(7,  1.0925484305920792f * (ux * uz))
                ACCY(8,  0.5462742152960396f * (ux2 - uy2))
                ACCY(9,  0.5900435899266435f * uy * (3.0f * ux2 - uy2))
                ACCY(10, 1.445305721320277f  * (2.0f * ux * uy * uz))
                ACCY(11, 0.4570457994644658f * uy * (5.0f * uz2 - 1.0f))
                ACCY(12, 0.3731763325901154f * uz * (5.0f * uz2 - 3.0f))
                ACCY(13, 0.4570457994644658f * ux * (5.0f * uz2 - 1.0f))
                ACCY(14, 1.445305721320277f  * (ux2 - uy2) * uz)
                ACCY(15, 0.5900435899266435f * ux * (ux2 - 3.0f * uy2))
                #undef ACCY

                if (!more) break;
                idx = nidx; cell = ncell; rv = nrv;
            }
        }
    }

    // ---------- block reduction: warp shfl tree then cross-warp ----------
    #pragma unroll
    for (int q = 0; q < NACC; ++q) {
        float v = acc[q];
        v += __shfl_xor_sync(0xFFFFFFFFu, v, 16);
        v += __shfl_xor_sync(0xFFFFFFFFu, v, 8);
        v += __shfl_xor_sync(0xFFFFFFFFu, v, 4);
        v += __shfl_xor_sync(0xFFFFFFFFu, v, 2);
        v += __shfl_xor_sync(0xFFFFFFFFu, v, 1);
        if (lane == 0) sred[warp][q] = v;
    }
    __syncthreads();
    if (tid < NACC / 2) {
        int q0 = tid, q1 = tid + 64;
        g_part[(atom * CSPLIT + split) * NACC + q0] = sred[0][q0] + sred[1][q0];
        g_part[(atom * CSPLIT + split) * NACC + q1] = sred[0][q1] + sred[1][q1];
    }

    // ---------- last-block-per-atom finalization (fp64, W * binomial-shift) ----------
    __threadfence();
    if (tid == 0) s_old = atomicAdd(&g_cnt[atom], 1);
    __syncthreads();
    if (s_old == CSPLIT - 1) {
        __threadfence();
        const int lm = tid & 15;
        const int nlo = tid >> 4;            // 0..3 ; also handles nlo+4

        // nu_k[lm] summed over splits, in double
        double vk[NRAD];
        #pragma unroll
        for (int k = 0; k < NRAD; ++k) {
            double a = 0.0;
            for (int sp = 0; sp < CSPLIT; ++sp)
                a += (double)g_part[(atom * CSPLIT + sp) * NACC + k * NANG + lm];
            vk[k] = a;
        }

        // mu_m = sum_k binom(m,k) c^{m-k} nu_k ; coeff_n = sum_m W[n,m] mu_m
        const double binom[NRAD][NRAD] = {
            {1,0,0,0,0,0,0,0},{1,1,0,0,0,0,0,0},{1,2,1,0,0,0,0,0},{1,3,3,1,0,0,0,0},
            {1,4,6,4,1,0,0,0},{1,5,10,10,5,1,0,0},{1,6,15,20,15,6,1,0},{1,7,21,35,35,21,7,1}};
        double cp[NRAD];
        cp[0] = 1.0;
        #pragma unroll
        for (int k = 1; k < NRAD; ++k) cp[k] = cp[k - 1] * (double)SHIFT_C;

        double mu[NRAD];
        #pragma unroll
        for (int m = 0; m < NRAD; ++m) {
            double a = 0.0;
            #pragma unroll
            for (int k = 0; k <= m; ++k) a += binom[m][k] * cp[m - k] * vk[k];
            mu[m] = a;
        }

        const double vcell = (36.0 / 180.0) * (36.0 / 180.0) * (36.0 / 180.0);
        #pragma unroll
        for (int h = 0; h < 2; ++h) {
            int n = nlo + 4 * h;
            double sacc = 0.0;
            #pragma unroll
            for (int m = 0; m < NRAD; ++m)
                sacc += (double)W[n * NRAD + m] * mu[m];
            out[atom * NACC + n * NANG + lm] = (float)(sacc * vcell);
        }
        if (tid == 0) g_cnt[atom] = 0;       // reset for graph replay
    }
}

extern "C" void kernel_launch(void* const* d_in, const int* in_sizes, int n_in,
                              void* d_out, int out_size)
{
    const float* rho = (const float*)d_in[0];   // [180,180,180]
    const float* pos = (const float*)d_in[1];   // [64,3]
    const float* W   = (const float*)d_in[2];   // [8,8]
    float* out = (float*)d_out;                 // [64,128]

    dim3 grid(CSPLIT, NATOMS);                  // 11 x 64 = 704 blocks
    proj_kernel<<<grid, NTH>>>(rho, pos, W, out);
}